// round 2
// baseline (speedup 1.0000x reference)
#include <cuda_runtime.h>
#include <math.h>

#define Bn   2
#define Sn   2048
#define En   1024
#define Hn   16
#define Dn   64
#define NEXP 8
#define NTOK (Bn*Sn)          // 4096

// ---------------- scratch (device globals; no allocation) ----------------
__device__ float g_lin [(size_t)3*NTOK*En];        // q,k,v after projection  (tok, E)
__device__ float g_rot [(size_t)3*Bn*Hn*Sn*Dn];    // q,k,v rotated/transposed (bh, s, d)
__device__ float g_attn[(size_t)NTOK*En];          // attention output (tok, E)
__device__ float g_sel [(size_t)2*NTOK*En];        // per (token,slot) expert output
__device__ float g_moe [(size_t)NTOK*En];          // combined MoE output
__device__ float g_gateflat[2*NTOK];               // gate prob per flat (token*2+slot)
__device__ int   g_list[NEXP*NTOK];                // per-expert flat indices
__device__ int   g_cnt [NEXP];

// ---------------- tiny utility kernels ----------------
__global__ void zero_cnt_kernel() {
    if (threadIdx.x < NEXP) g_cnt[threadIdx.x] = 0;
}

// ---------------- generic SGEMM-TN: C[m,n] = sum_k A[m,k]*W[n,k] + bias[n] (+resid) ----------------
// a_mode: 0 -> use A param, 1 -> A = g_moe
// c_mode: 0 -> use C param, 1/2/3 -> C = g_lin + (c_mode-1)*NTOK*En
__global__ void __launch_bounds__(256, 2)
sgemm_tn(const float* __restrict__ A, const float* __restrict__ W,
         const float* __restrict__ bias, const float* __restrict__ resid,
         float* __restrict__ C, int M, int N, int K, int a_mode, int c_mode)
{
    __shared__ float As[16][128];
    __shared__ float Bs[16][128];

    const float* Ap = (a_mode == 0) ? A : g_moe;
    float*       Cp = (c_mode == 0) ? C : (g_lin + (size_t)(c_mode - 1) * NTOK * En);

    const int tid = threadIdx.x;
    const int m0  = blockIdx.y * 128;
    const int n0  = blockIdx.x * 128;
    const int tx  = tid & 15;
    const int ty  = tid >> 4;

    float acc[8][8];
    #pragma unroll
    for (int i = 0; i < 8; i++)
        #pragma unroll
        for (int j = 0; j < 8; j++) acc[i][j] = 0.f;

    for (int kt = 0; kt < K; kt += 16) {
        #pragma unroll
        for (int l = 0; l < 2; l++) {
            int f4  = l * 256 + tid;          // 0..511
            int row = f4 >> 2;
            int kc  = (f4 & 3) << 2;
            float4 a = *(const float4*)(Ap + (size_t)(m0 + row) * K + kt + kc);
            As[kc + 0][row] = a.x; As[kc + 1][row] = a.y;
            As[kc + 2][row] = a.z; As[kc + 3][row] = a.w;
            float4 b = *(const float4*)(W + (size_t)(n0 + row) * K + kt + kc);
            Bs[kc + 0][row] = b.x; Bs[kc + 1][row] = b.y;
            Bs[kc + 2][row] = b.z; Bs[kc + 3][row] = b.w;
        }
        __syncthreads();
        #pragma unroll
        for (int k = 0; k < 16; k++) {
            float ar[8], br[8];
            const float4* ap4 = (const float4*)&As[k][ty * 8];
            const float4* bp4 = (const float4*)&Bs[k][tx * 8];
            float4 a0 = ap4[0], a1 = ap4[1];
            float4 b0 = bp4[0], b1 = bp4[1];
            ar[0]=a0.x; ar[1]=a0.y; ar[2]=a0.z; ar[3]=a0.w;
            ar[4]=a1.x; ar[5]=a1.y; ar[6]=a1.z; ar[7]=a1.w;
            br[0]=b0.x; br[1]=b0.y; br[2]=b0.z; br[3]=b0.w;
            br[4]=b1.x; br[5]=b1.y; br[6]=b1.z; br[7]=b1.w;
            #pragma unroll
            for (int i = 0; i < 8; i++)
                #pragma unroll
                for (int j = 0; j < 8; j++)
                    acc[i][j] += ar[i] * br[j];
        }
        __syncthreads();
    }

    const bool has_res = (resid != nullptr);
    #pragma unroll
    for (int i = 0; i < 8; i++) {
        const int m = m0 + ty * 8 + i;
        float* crow = Cp + (size_t)m * N + n0 + tx * 8;
        const float* brow = bias + n0 + tx * 8;
        float v[8];
        #pragma unroll
        for (int j = 0; j < 8; j++) v[j] = acc[i][j] + brow[j];
        if (has_res) {
            const float* rrow = resid + (size_t)m * N + n0 + tx * 8;
            #pragma unroll
            for (int j = 0; j < 8; j++) v[j] += rrow[j];
        }
        *(float4*)(crow)     = make_float4(v[0], v[1], v[2], v[3]);
        *(float4*)(crow + 4) = make_float4(v[4], v[5], v[6], v[7]);
    }
}

// ---------------- RoPE + transpose: (tok, h*64+d) -> (bh, s, d) ----------------
__global__ void rope_transpose_kernel()
{
    int idx = blockIdx.x * blockDim.x + threadIdx.x;   // B*S*H*32 = 2^21 threads
    int i = idx & 31;
    int h = (idx >> 5) & 15;
    int s = (idx >> 9) & (Sn - 1);
    int b = idx >> 20;

    float expo = (float)(2 * i) / 64.0f;
    float inv  = powf(10000.0f, -expo);
    float ang  = (float)s * inv;
    float sn, cs;
    sincosf(ang, &sn, &cs);

    size_t in_base  = ((size_t)(b * Sn + s)) * En + h * 64;
    size_t out_base = ((size_t)((b * Hn + h) * Sn + s)) * 64;
    const size_t lin_stride = (size_t)NTOK * En;
    const size_t rot_stride = (size_t)Bn * Hn * Sn * Dn;

    // q
    {
        const float* src = g_lin + in_base;
        float x1 = src[i], x2 = src[i + 32];
        g_rot[out_base + i]      = x1 * cs - x2 * sn;
        g_rot[out_base + i + 32] = x2 * cs + x1 * sn;
    }
    // k
    {
        const float* src = g_lin + lin_stride + in_base;
        float x1 = src[i], x2 = src[i + 32];
        g_rot[rot_stride + out_base + i]      = x1 * cs - x2 * sn;
        g_rot[rot_stride + out_base + i + 32] = x2 * cs + x1 * sn;
    }
    // v (transpose only)
    {
        const float* src = g_lin + 2 * lin_stride + in_base;
        g_rot[2 * rot_stride + out_base + i]      = src[i];
        g_rot[2 * rot_stride + out_base + i + 32] = src[i + 32];
    }
}

// ---------------- flash attention: 1 thread = 1 query row ----------------
__global__ void __launch_bounds__(128)
attn_kernel()
{
    const int bh  = blockIdx.y;            // 0..31
    const int q0  = blockIdx.x * 128;
    const int tid = threadIdx.x;
    const size_t rot_stride = (size_t)Bn * Hn * Sn * Dn;
    const float* Qr = g_rot;
    const float* Kr = g_rot + rot_stride;
    const float* Vr = g_rot + 2 * rot_stride;
    const size_t base = (size_t)bh * Sn * Dn;

    __shared__ float Ks[64][64];
    __shared__ float Vs[64][64];

    float q[64], o[64];
    {
        const float4* qp = (const float4*)(Qr + base + (size_t)(q0 + tid) * 64);
        #pragma unroll
        for (int i = 0; i < 16; i++) {
            float4 t = qp[i];
            q[4*i+0] = t.x * 0.125f; q[4*i+1] = t.y * 0.125f;
            q[4*i+2] = t.z * 0.125f; q[4*i+3] = t.w * 0.125f;
        }
    }
    #pragma unroll
    for (int d = 0; d < 64; d++) o[d] = 0.f;
    float mx = -1e30f, l = 0.f;

    #pragma unroll 1
    for (int kt = 0; kt < Sn; kt += 64) {
        __syncthreads();
        const float4* kp = (const float4*)(Kr + base + (size_t)kt * 64);
        const float4* vp = (const float4*)(Vr + base + (size_t)kt * 64);
        float4* ks4 = (float4*)&Ks[0][0];
        float4* vs4 = (float4*)&Vs[0][0];
        #pragma unroll
        for (int i = 0; i < 8; i++) {
            int f4 = i * 128 + tid;            // 0..1023
            ks4[f4] = kp[f4];
            vs4[f4] = vp[f4];
        }
        __syncthreads();

        #pragma unroll 1
        for (int j0 = 0; j0 < 64; j0 += 16) {
            float s[16];
            #pragma unroll
            for (int j = 0; j < 16; j++) {
                const float4* kr = (const float4*)&Ks[j0 + j][0];
                float a0 = 0.f, a1 = 0.f, a2 = 0.f, a3 = 0.f;
                #pragma unroll
                for (int d4 = 0; d4 < 16; d4++) {
                    float4 kv = kr[d4];
                    a0 += q[4*d4+0] * kv.x; a1 += q[4*d4+1] * kv.y;
                    a2 += q[4*d4+2] * kv.z; a3 += q[4*d4+3] * kv.w;
                }
                s[j] = (a0 + a1) + (a2 + a3);
            }
            float tm = mx;
            #pragma unroll
            for (int j = 0; j < 16; j++) tm = fmaxf(tm, s[j]);
            float corr = __expf(mx - tm);
            mx = tm;
            l *= corr;
            #pragma unroll
            for (int d = 0; d < 64; d++) o[d] *= corr;
            #pragma unroll
            for (int j = 0; j < 16; j++) {
                float p = __expf(s[j] - mx);
                l += p;
                const float4* vr = (const float4*)&Vs[j0 + j][0];
                #pragma unroll
                for (int d4 = 0; d4 < 16; d4++) {
                    float4 vv = vr[d4];
                    o[4*d4+0] += p * vv.x; o[4*d4+1] += p * vv.y;
                    o[4*d4+2] += p * vv.z; o[4*d4+3] += p * vv.w;
                }
            }
        }
    }

    float invl = 1.f / l;
    int b = bh / Hn, h = bh % Hn;
    float4* op = (float4*)(g_attn + ((size_t)(b * Sn + q0 + tid)) * En + h * 64);
    #pragma unroll
    for (int i = 0; i < 16; i++) {
        float4 t;
        t.x = o[4*i+0] * invl; t.y = o[4*i+1] * invl;
        t.z = o[4*i+2] * invl; t.w = o[4*i+3] * invl;
        op[i] = t;
    }
}

// ---------------- gate logits + softmax + top-2 + dispatch ----------------
__global__ void __launch_bounds__(128)
gate_topk_kernel(const float* __restrict__ gw, const float* __restrict__ gb)
{
    const int warp = threadIdx.x >> 5;
    const int lane = threadIdx.x & 31;
    const int t = blockIdx.x * 4 + warp;

    float acc[NEXP];
    #pragma unroll
    for (int e = 0; e < NEXP; e++) acc[e] = 0.f;
    const float* xr = g_attn + (size_t)t * En;
    for (int i = lane; i < En; i += 32) {
        float xv = xr[i];
        #pragma unroll
        for (int e = 0; e < NEXP; e++) acc[e] += xv * gw[e * En + i];
    }
    #pragma unroll
    for (int e = 0; e < NEXP; e++) {
        #pragma unroll
        for (int off = 16; off; off >>= 1)
            acc[e] += __shfl_xor_sync(0xffffffffu, acc[e], off);
    }
    if (lane == 0) {
        float lg[NEXP];
        float m = -1e30f;
        #pragma unroll
        for (int e = 0; e < NEXP; e++) { lg[e] = acc[e] + gb[e]; m = fmaxf(m, lg[e]); }
        float sum = 0.f;
        #pragma unroll
        for (int e = 0; e < NEXP; e++) { lg[e] = __expf(lg[e] - m); sum += lg[e]; }
        float invs = 1.f / sum;
        int i0 = 0;
        #pragma unroll
        for (int e = 1; e < NEXP; e++) if (lg[e] > lg[i0]) i0 = e;
        int i1 = (i0 == 0) ? 1 : 0;
        #pragma unroll
        for (int e = 0; e < NEXP; e++) if (e != i0 && lg[e] > lg[i1]) i1 = e;

        int p0 = atomicAdd(&g_cnt[i0], 1);
        g_list[i0 * NTOK + p0] = t * 2;
        g_gateflat[t * 2] = lg[i0] * invs;
        int p1 = atomicAdd(&g_cnt[i1], 1);
        g_list[i1 * NTOK + p1] = t * 2 + 1;
        g_gateflat[t * 2 + 1] = lg[i1] * invs;
    }
}

// ---------------- grouped expert GEMM (gathered rows) ----------------
__global__ void __launch_bounds__(256, 2)
expert_gemm_kernel(const float* __restrict__ ew, const float* __restrict__ eb)
{
    const int e   = blockIdx.z;
    const int cnt = g_cnt[e];
    const int m0  = blockIdx.y * 128;
    if (m0 >= cnt) return;
    const int n0  = blockIdx.x * 128;

    __shared__ float As[16][128];
    __shared__ float Bs[16][128];
    __shared__ int   rowflat[128];
    __shared__ float rowgate[128];

    const int tid = threadIdx.x;
    if (tid < 128) {
        int m = m0 + tid;
        int fl = (m < cnt) ? g_list[e * NTOK + m] : 0;
        rowflat[tid] = fl;
        rowgate[tid] = (m < cnt) ? g_gateflat[fl] : 0.f;
    }
    __syncthreads();

    const float* W = ew + (size_t)e * En * En;
    const int tx = tid & 15;
    const int ty = tid >> 4;
    float acc[8][8];
    #pragma unroll
    for (int i = 0; i < 8; i++)
        #pragma unroll
        for (int j = 0; j < 8; j++) acc[i][j] = 0.f;

    for (int kt = 0; kt < En; kt += 16) {
        #pragma unroll
        for (int l = 0; l < 2; l++) {
            int f4  = l * 256 + tid;
            int row = f4 >> 2;
            int kc  = (f4 & 3) << 2;
            int tok = rowflat[row] >> 1;
            float4 a = *(const float4*)(g_attn + (size_t)tok * En + kt + kc);
            As[kc + 0][row] = a.x; As[kc + 1][row] = a.y;
            As[kc + 2][row] = a.z; As[kc + 3][row] = a.w;
            float4 b = *(const float4*)(W + (size_t)(n0 + row) * En + kt + kc);
            Bs[kc + 0][row] = b.x; Bs[kc + 1][row] = b.y;
            Bs[kc + 2][row] = b.z; Bs[kc + 3][row] = b.w;
        }
        __syncthreads();
        #pragma unroll
        for (int k = 0; k < 16; k++) {
            float ar[8], br[8];
            const float4* ap4 = (const float4*)&As[k][ty * 8];
            const float4* bp4 = (const float4*)&Bs[k][tx * 8];
            float4 a0 = ap4[0], a1 = ap4[1];
            float4 b0 = bp4[0], b1 = bp4[1];
            ar[0]=a0.x; ar[1]=a0.y; ar[2]=a0.z; ar[3]=a0.w;
            ar[4]=a1.x; ar[5]=a1.y; ar[6]=a1.z; ar[7]=a1.w;
            br[0]=b0.x; br[1]=b0.y; br[2]=b0.z; br[3]=b0.w;
            br[4]=b1.x; br[5]=b1.y; br[6]=b1.z; br[7]=b1.w;
            #pragma unroll
            for (int i = 0; i < 8; i++)
                #pragma unroll
                for (int j = 0; j < 8; j++)
                    acc[i][j] += ar[i] * br[j];
        }
        __syncthreads();
    }

    #pragma unroll
    for (int i = 0; i < 8; i++) {
        const int mloc = ty * 8 + i;
        if (m0 + mloc >= cnt) continue;
        const int fl = rowflat[mloc];
        const float gtv = rowgate[mloc];
        float* crow = g_sel + (size_t)fl * En + n0 + tx * 8;
        const float* brow = eb + (size_t)e * En + n0 + tx * 8;
        float v[8];
        #pragma unroll
        for (int j = 0; j < 8; j++) v[j] = gtv * (acc[i][j] + brow[j]);
        *(float4*)(crow)     = make_float4(v[0], v[1], v[2], v[3]);
        *(float4*)(crow + 4) = make_float4(v[4], v[5], v[6], v[7]);
    }
}

// ---------------- combine two expert slots ----------------
__global__ void combine_kernel()
{
    size_t i = (size_t)blockIdx.x * blockDim.x + threadIdx.x;  // over NTOK*256
    size_t row = i >> 8;
    size_t col = i & 255;
    const float4* s4 = (const float4*)g_sel;
    float4 a = s4[(2 * row) * 256 + col];
    float4 b = s4[(2 * row + 1) * 256 + col];
    float4 r;
    r.x = a.x + b.x; r.y = a.y + b.y; r.z = a.z + b.z; r.w = a.w + b.w;
    ((float4*)g_moe)[i] = r;
}

// ---------------- launch ----------------
extern "C" void kernel_launch(void* const* d_in, const int* in_sizes, int n_in,
                              void* d_out, int out_size)
{
    const float* x     = (const float*)d_in[0];
    const float* q_w   = (const float*)d_in[1];
    const float* q_b   = (const float*)d_in[2];
    const float* k_w   = (const float*)d_in[3];
    const float* k_b   = (const float*)d_in[4];
    const float* v_w   = (const float*)d_in[5];
    const float* v_b   = (const float*)d_in[6];
    const float* gatew = (const float*)d_in[7];
    const float* gateb = (const float*)d_in[8];
    const float* ew    = (const float*)d_in[9];
    const float* eb    = (const float*)d_in[10];
    const float* ffn_w = (const float*)d_in[11];
    const float* ffn_b = (const float*)d_in[12];
    float* out = (float*)d_out;

    dim3 gemm_grid(En / 128, NTOK / 128);   // (8, 32)

    zero_cnt_kernel<<<1, 32>>>();

    // Q, K, V projections -> g_lin slices (c_mode 1..3)
    sgemm_tn<<<gemm_grid, 256>>>(x, q_w, q_b, nullptr, nullptr, NTOK, En, En, 0, 1);
    sgemm_tn<<<gemm_grid, 256>>>(x, k_w, k_b, nullptr, nullptr, NTOK, En, En, 0, 2);
    sgemm_tn<<<gemm_grid, 256>>>(x, v_w, v_b, nullptr, nullptr, NTOK, En, En, 0, 3);

    rope_transpose_kernel<<<(Bn * Sn * Hn * 32) / 256, 256>>>();

    attn_kernel<<<dim3(Sn / 128, Bn * Hn), 128>>>();

    gate_topk_kernel<<<NTOK / 4, 128>>>(gatew, gateb);

    expert_gemm_kernel<<<dim3(En / 128, NTOK / 128, NEXP), 256>>>(ew, eb);

    combine_kernel<<<(NTOK * (En / 4)) / 256, 256>>>();

    // final FFN + bias + residual -> d_out  (a_mode=1: A = g_moe)
    sgemm_tn<<<gemm_grid, 256>>>(nullptr, ffn_w, ffn_b, x, out, NTOK, En, En, 1, 0);
}

// round 3
// speedup vs baseline: 1.0009x; 1.0009x over previous
#include <cuda_runtime.h>
#include <math.h>

#define Bn   2
#define Sn   2048
#define En   1024
#define Hn   16
#define Dn   64
#define NEXP 8
#define NTOK (Bn*Sn)          // 4096

// ---------------- scratch (device globals; no allocation) ----------------
__device__ float g_lin [(size_t)3*NTOK*En];        // q,k,v after projection  (tok, E)
__device__ float g_rot [(size_t)3*Bn*Hn*Sn*Dn];    // q,k,v rotated/transposed (bh, s, d)
__device__ float g_attn[(size_t)NTOK*En];          // attention output (tok, E)
__device__ float g_sel [(size_t)2*NTOK*En];        // per (token,slot) expert output
__device__ float g_moe [(size_t)NTOK*En];          // combined MoE output
__device__ float g_gateflat[2*NTOK];               // gate prob per flat (token*2+slot)
__device__ int   g_list[NEXP*NTOK];                // per-expert flat indices
__device__ int   g_cnt [NEXP];

// ---------------- tiny utility kernels ----------------
__global__ void zero_cnt_kernel() {
    if (threadIdx.x < NEXP) g_cnt[threadIdx.x] = 0;
}

// ---------------- generic SGEMM-TN: C[m,n] = sum_k A[m,k]*W[n,k] + bias[n] (+resid) ----------------
// a_mode: 0 -> use A param, 1 -> A = g_moe
// c_mode: 0 -> use C param, 1/2/3 -> C = g_lin + (c_mode-1)*NTOK*En
__global__ void __launch_bounds__(256, 2)
sgemm_tn(const float* __restrict__ A, const float* __restrict__ W,
         const float* __restrict__ bias, const float* __restrict__ resid,
         float* __restrict__ C, int M, int N, int K, int a_mode, int c_mode)
{
    __shared__ float As[16][128];
    __shared__ float Bs[16][128];

    const float* Ap = (a_mode == 0) ? A : g_moe;
    float*       Cp = (c_mode == 0) ? C : (g_lin + (size_t)(c_mode - 1) * NTOK * En);

    const int tid = threadIdx.x;
    const int m0  = blockIdx.y * 128;
    const int n0  = blockIdx.x * 128;
    const int tx  = tid & 15;
    const int ty  = tid >> 4;

    float acc[8][8];
    #pragma unroll
    for (int i = 0; i < 8; i++)
        #pragma unroll
        for (int j = 0; j < 8; j++) acc[i][j] = 0.f;

    for (int kt = 0; kt < K; kt += 16) {
        #pragma unroll
        for (int l = 0; l < 2; l++) {
            int f4  = l * 256 + tid;          // 0..511
            int row = f4 >> 2;
            int kc  = (f4 & 3) << 2;
            float4 a = *(const float4*)(Ap + (size_t)(m0 + row) * K + kt + kc);
            As[kc + 0][row] = a.x; As[kc + 1][row] = a.y;
            As[kc + 2][row] = a.z; As[kc + 3][row] = a.w;
            float4 b = *(const float4*)(W + (size_t)(n0 + row) * K + kt + kc);
            Bs[kc + 0][row] = b.x; Bs[kc + 1][row] = b.y;
            Bs[kc + 2][row] = b.z; Bs[kc + 3][row] = b.w;
        }
        __syncthreads();
        #pragma unroll
        for (int k = 0; k < 16; k++) {
            float ar[8], br[8];
            const float4* ap4 = (const float4*)&As[k][ty * 8];
            const float4* bp4 = (const float4*)&Bs[k][tx * 8];
            float4 a0 = ap4[0], a1 = ap4[1];
            float4 b0 = bp4[0], b1 = bp4[1];
            ar[0]=a0.x; ar[1]=a0.y; ar[2]=a0.z; ar[3]=a0.w;
            ar[4]=a1.x; ar[5]=a1.y; ar[6]=a1.z; ar[7]=a1.w;
            br[0]=b0.x; br[1]=b0.y; br[2]=b0.z; br[3]=b0.w;
            br[4]=b1.x; br[5]=b1.y; br[6]=b1.z; br[7]=b1.w;
            #pragma unroll
            for (int i = 0; i < 8; i++)
                #pragma unroll
                for (int j = 0; j < 8; j++)
                    acc[i][j] += ar[i] * br[j];
        }
        __syncthreads();
    }

    const bool has_res = (resid != nullptr);
    #pragma unroll
    for (int i = 0; i < 8; i++) {
        const int m = m0 + ty * 8 + i;
        float* crow = Cp + (size_t)m * N + n0 + tx * 8;
        const float* brow = bias + n0 + tx * 8;
        float v[8];
        #pragma unroll
        for (int j = 0; j < 8; j++) v[j] = acc[i][j] + brow[j];
        if (has_res) {
            const float* rrow = resid + (size_t)m * N + n0 + tx * 8;
            #pragma unroll
            for (int j = 0; j < 8; j++) v[j] += rrow[j];
        }
        *(float4*)(crow)     = make_float4(v[0], v[1], v[2], v[3]);
        *(float4*)(crow + 4) = make_float4(v[4], v[5], v[6], v[7]);
    }
}

// ---------------- RoPE + transpose: (tok, h*64+d) -> (bh, s, d) ----------------
__global__ void rope_transpose_kernel()
{
    int idx = blockIdx.x * blockDim.x + threadIdx.x;   // B*S*H*32 = 2^21 threads
    int i = idx & 31;
    int h = (idx >> 5) & 15;
    int s = (idx >> 9) & (Sn - 1);
    int b = idx >> 20;

    float expo = (float)(2 * i) / 64.0f;
    float inv  = powf(10000.0f, -expo);
    float ang  = (float)s * inv;
    float sn, cs;
    sincosf(ang, &sn, &cs);

    size_t in_base  = ((size_t)(b * Sn + s)) * En + h * 64;
    size_t out_base = ((size_t)((b * Hn + h) * Sn + s)) * 64;
    const size_t lin_stride = (size_t)NTOK * En;
    const size_t rot_stride = (size_t)Bn * Hn * Sn * Dn;

    // q
    {
        const float* src = g_lin + in_base;
        float x1 = src[i], x2 = src[i + 32];
        g_rot[out_base + i]      = x1 * cs - x2 * sn;
        g_rot[out_base + i + 32] = x2 * cs + x1 * sn;
    }
    // k
    {
        const float* src = g_lin + lin_stride + in_base;
        float x1 = src[i], x2 = src[i + 32];
        g_rot[rot_stride + out_base + i]      = x1 * cs - x2 * sn;
        g_rot[rot_stride + out_base + i + 32] = x2 * cs + x1 * sn;
    }
    // v (transpose only)
    {
        const float* src = g_lin + 2 * lin_stride + in_base;
        g_rot[2 * rot_stride + out_base + i]      = src[i];
        g_rot[2 * rot_stride + out_base + i + 32] = src[i + 32];
    }
}

// ---------------- flash attention: 1 thread = 1 query row ----------------
__global__ void __launch_bounds__(128)
attn_kernel()
{
    const int bh  = blockIdx.y;            // 0..31
    const int q0  = blockIdx.x * 128;
    const int tid = threadIdx.x;
    const size_t rot_stride = (size_t)Bn * Hn * Sn * Dn;
    const float* Qr = g_rot;
    const float* Kr = g_rot + rot_stride;
    const float* Vr = g_rot + 2 * rot_stride;
    const size_t base = (size_t)bh * Sn * Dn;

    __shared__ float Ks[64][64];
    __shared__ float Vs[64][64];

    float q[64], o[64];
    {
        const float4* qp = (const float4*)(Qr + base + (size_t)(q0 + tid) * 64);
        #pragma unroll
        for (int i = 0; i < 16; i++) {
            float4 t = qp[i];
            q[4*i+0] = t.x * 0.125f; q[4*i+1] = t.y * 0.125f;
            q[4*i+2] = t.z * 0.125f; q[4*i+3] = t.w * 0.125f;
        }
    }
    #pragma unroll
    for (int d = 0; d < 64; d++) o[d] = 0.f;
    float mx = -1e30f, l = 0.f;

    #pragma unroll 1
    for (int kt = 0; kt < Sn; kt += 64) {
        __syncthreads();
        const float4* kp = (const float4*)(Kr + base + (size_t)kt * 64);
        const float4* vp = (const float4*)(Vr + base + (size_t)kt * 64);
        float4* ks4 = (float4*)&Ks[0][0];
        float4* vs4 = (float4*)&Vs[0][0];
        #pragma unroll
        for (int i = 0; i < 8; i++) {
            int f4 = i * 128 + tid;            // 0..1023
            ks4[f4] = kp[f4];
            vs4[f4] = vp[f4];
        }
        __syncthreads();

        #pragma unroll 1
        for (int j0 = 0; j0 < 64; j0 += 16) {
            float s[16];
            #pragma unroll
            for (int j = 0; j < 16; j++) {
                const float4* kr = (const float4*)&Ks[j0 + j][0];
                float a0 = 0.f, a1 = 0.f, a2 = 0.f, a3 = 0.f;
                #pragma unroll
                for (int d4 = 0; d4 < 16; d4++) {
                    float4 kv = kr[d4];
                    a0 += q[4*d4+0] * kv.x; a1 += q[4*d4+1] * kv.y;
                    a2 += q[4*d4+2] * kv.z; a3 += q[4*d4+3] * kv.w;
                }
                s[j] = (a0 + a1) + (a2 + a3);
            }
            float tm = mx;
            #pragma unroll
            for (int j = 0; j < 16; j++) tm = fmaxf(tm, s[j]);
            float corr = __expf(mx - tm);
            mx = tm;
            l *= corr;
            #pragma unroll
            for (int d = 0; d < 64; d++) o[d] *= corr;
            #pragma unroll
            for (int j = 0; j < 16; j++) {
                float p = __expf(s[j] - mx);
                l += p;
                const float4* vr = (const float4*)&Vs[j0 + j][0];
                #pragma unroll
                for (int d4 = 0; d4 < 16; d4++) {
                    float4 vv = vr[d4];
                    o[4*d4+0] += p * vv.x; o[4*d4+1] += p * vv.y;
                    o[4*d4+2] += p * vv.z; o[4*d4+3] += p * vv.w;
                }
            }
        }
    }

    float invl = 1.f / l;
    int b = bh / Hn, h = bh % Hn;
    float4* op = (float4*)(g_attn + ((size_t)(b * Sn + q0 + tid)) * En + h * 64);
    #pragma unroll
    for (int i = 0; i < 16; i++) {
        float4 t;
        t.x = o[4*i+0] * invl; t.y = o[4*i+1] * invl;
        t.z = o[4*i+2] * invl; t.w = o[4*i+3] * invl;
        op[i] = t;
    }
}

// ---------------- gate logits + softmax + top-2 + dispatch ----------------
__global__ void __launch_bounds__(128)
gate_topk_kernel(const float* __restrict__ gw, const float* __restrict__ gb)
{
    const int warp = threadIdx.x >> 5;
    const int lane = threadIdx.x & 31;
    const int t = blockIdx.x * 4 + warp;

    float acc[NEXP];
    #pragma unroll
    for (int e = 0; e < NEXP; e++) acc[e] = 0.f;
    const float* xr = g_attn + (size_t)t * En;
    for (int i = lane; i < En; i += 32) {
        float xv = xr[i];
        #pragma unroll
        for (int e = 0; e < NEXP; e++) acc[e] += xv * gw[e * En + i];
    }
    #pragma unroll
    for (int e = 0; e < NEXP; e++) {
        #pragma unroll
        for (int off = 16; off; off >>= 1)
            acc[e] += __shfl_xor_sync(0xffffffffu, acc[e], off);
    }
    if (lane == 0) {
        float lg[NEXP];
        float m = -1e30f;
        #pragma unroll
        for (int e = 0; e < NEXP; e++) { lg[e] = acc[e] + gb[e]; m = fmaxf(m, lg[e]); }
        float sum = 0.f;
        #pragma unroll
        for (int e = 0; e < NEXP; e++) { lg[e] = __expf(lg[e] - m); sum += lg[e]; }
        float invs = 1.f / sum;
        int i0 = 0;
        #pragma unroll
        for (int e = 1; e < NEXP; e++) if (lg[e] > lg[i0]) i0 = e;
        int i1 = (i0 == 0) ? 1 : 0;
        #pragma unroll
        for (int e = 0; e < NEXP; e++) if (e != i0 && lg[e] > lg[i1]) i1 = e;

        int p0 = atomicAdd(&g_cnt[i0], 1);
        g_list[i0 * NTOK + p0] = t * 2;
        g_gateflat[t * 2] = lg[i0] * invs;
        int p1 = atomicAdd(&g_cnt[i1], 1);
        g_list[i1 * NTOK + p1] = t * 2 + 1;
        g_gateflat[t * 2 + 1] = lg[i1] * invs;
    }
}

// ---------------- grouped expert GEMM (gathered rows) ----------------
__global__ void __launch_bounds__(256, 2)
expert_gemm_kernel(const float* __restrict__ ew, const float* __restrict__ eb)
{
    const int e   = blockIdx.z;
    const int cnt = g_cnt[e];
    const int m0  = blockIdx.y * 128;
    if (m0 >= cnt) return;
    const int n0  = blockIdx.x * 128;

    __shared__ float As[16][128];
    __shared__ float Bs[16][128];
    __shared__ int   rowflat[128];
    __shared__ float rowgate[128];

    const int tid = threadIdx.x;
    if (tid < 128) {
        int m = m0 + tid;
        int fl = (m < cnt) ? g_list[e * NTOK + m] : 0;
        rowflat[tid] = fl;
        rowgate[tid] = (m < cnt) ? g_gateflat[fl] : 0.f;
    }
    __syncthreads();

    const float* W = ew + (size_t)e * En * En;
    const int tx = tid & 15;
    const int ty = tid >> 4;
    float acc[8][8];
    #pragma unroll
    for (int i = 0; i < 8; i++)
        #pragma unroll
        for (int j = 0; j < 8; j++) acc[i][j] = 0.f;

    for (int kt = 0; kt < En; kt += 16) {
        #pragma unroll
        for (int l = 0; l < 2; l++) {
            int f4  = l * 256 + tid;
            int row = f4 >> 2;
            int kc  = (f4 & 3) << 2;
            int tok = rowflat[row] >> 1;
            float4 a = *(const float4*)(g_attn + (size_t)tok * En + kt + kc);
            As[kc + 0][row] = a.x; As[kc + 1][row] = a.y;
            As[kc + 2][row] = a.z; As[kc + 3][row] = a.w;
            float4 b = *(const float4*)(W + (size_t)(n0 + row) * En + kt + kc);
            Bs[kc + 0][row] = b.x; Bs[kc + 1][row] = b.y;
            Bs[kc + 2][row] = b.z; Bs[kc + 3][row] = b.w;
        }
        __syncthreads();
        #pragma unroll
        for (int k = 0; k < 16; k++) {
            float ar[8], br[8];
            const float4* ap4 = (const float4*)&As[k][ty * 8];
            const float4* bp4 = (const float4*)&Bs[k][tx * 8];
            float4 a0 = ap4[0], a1 = ap4[1];
            float4 b0 = bp4[0], b1 = bp4[1];
            ar[0]=a0.x; ar[1]=a0.y; ar[2]=a0.z; ar[3]=a0.w;
            ar[4]=a1.x; ar[5]=a1.y; ar[6]=a1.z; ar[7]=a1.w;
            br[0]=b0.x; br[1]=b0.y; br[2]=b0.z; br[3]=b0.w;
            br[4]=b1.x; br[5]=b1.y; br[6]=b1.z; br[7]=b1.w;
            #pragma unroll
            for (int i = 0; i < 8; i++)
                #pragma unroll
                for (int j = 0; j < 8; j++)
                    acc[i][j] += ar[i] * br[j];
        }
        __syncthreads();
    }

    #pragma unroll
    for (int i = 0; i < 8; i++) {
        const int mloc = ty * 8 + i;
        if (m0 + mloc >= cnt) continue;
        const int fl = rowflat[mloc];
        const float gtv = rowgate[mloc];
        float* crow = g_sel + (size_t)fl * En + n0 + tx * 8;
        const float* brow = eb + (size_t)e * En + n0 + tx * 8;
        float v[8];
        #pragma unroll
        for (int j = 0; j < 8; j++) v[j] = gtv * (acc[i][j] + brow[j]);
        *(float4*)(crow)     = make_float4(v[0], v[1], v[2], v[3]);
        *(float4*)(crow + 4) = make_float4(v[4], v[5], v[6], v[7]);
    }
}

// ---------------- combine two expert slots ----------------
__global__ void combine_kernel()
{
    size_t i = (size_t)blockIdx.x * blockDim.x + threadIdx.x;  // over NTOK*256
    size_t row = i >> 8;
    size_t col = i & 255;
    const float4* s4 = (const float4*)g_sel;
    float4 a = s4[(2 * row) * 256 + col];
    float4 b = s4[(2 * row + 1) * 256 + col];
    float4 r;
    r.x = a.x + b.x; r.y = a.y + b.y; r.z = a.z + b.z; r.w = a.w + b.w;
    ((float4*)g_moe)[i] = r;
}

// ---------------- launch ----------------
extern "C" void kernel_launch(void* const* d_in, const int* in_sizes, int n_in,
                              void* d_out, int out_size)
{
    const float* x     = (const float*)d_in[0];
    const float* q_w   = (const float*)d_in[1];
    const float* q_b   = (const float*)d_in[2];
    const float* k_w   = (const float*)d_in[3];
    const float* k_b   = (const float*)d_in[4];
    const float* v_w   = (const float*)d_in[5];
    const float* v_b   = (const float*)d_in[6];
    const float* gatew = (const float*)d_in[7];
    const float* gateb = (const float*)d_in[8];
    const float* ew    = (const float*)d_in[9];
    const float* eb    = (const float*)d_in[10];
    const float* ffn_w = (const float*)d_in[11];
    const float* ffn_b = (const float*)d_in[12];
    float* out = (float*)d_out;

    dim3 gemm_grid(En / 128, NTOK / 128);   // (8, 32)

    zero_cnt_kernel<<<1, 32>>>();

    // Q, K, V projections -> g_lin slices (c_mode 1..3)
    sgemm_tn<<<gemm_grid, 256>>>(x, q_w, q_b, nullptr, nullptr, NTOK, En, En, 0, 1);
    sgemm_tn<<<gemm_grid, 256>>>(x, k_w, k_b, nullptr, nullptr, NTOK, En, En, 0, 2);
    sgemm_tn<<<gemm_grid, 256>>>(x, v_w, v_b, nullptr, nullptr, NTOK, En, En, 0, 3);

    rope_transpose_kernel<<<(Bn * Sn * Hn * 32) / 256, 256>>>();

    attn_kernel<<<dim3(Sn / 128, Bn * Hn), 128>>>();

    gate_topk_kernel<<<NTOK / 4, 128>>>(gatew, gateb);

    expert_gemm_kernel<<<dim3(En / 128, NTOK / 128, NEXP), 256>>>(ew, eb);

    combine_kernel<<<(NTOK * (En / 4)) / 256, 256>>>();

    // final FFN + bias + residual -> d_out  (a_mode=1: A = g_moe)
    sgemm_tn<<<gemm_grid, 256>>>(nullptr, ffn_w, ffn_b, x, out, NTOK, En, En, 1, 0);
}

// round 4
// speedup vs baseline: 1.0032x; 1.0023x over previous
#include <cuda_runtime.h>
#include <math.h>

#define Bn   2
#define Sn   2048
#define En   1024
#define Hn   16
#define Dn   64
#define NEXP 8
#define NTOK (Bn*Sn)          // 4096

// ---------------- scratch (device globals; no allocation) ----------------
__device__ float g_lin [(size_t)3*NTOK*En];        // q,k,v after projection  (tok, E)
__device__ float g_rot [(size_t)3*Bn*Hn*Sn*Dn];    // q,k,v rotated/transposed (bh, s, d)
__device__ float g_attn[(size_t)NTOK*En];          // attention output (tok, E)
__device__ float g_sel [(size_t)2*NTOK*En];        // per (token,slot) expert output
__device__ float g_moe [(size_t)NTOK*En];          // combined MoE output
__device__ float g_gateflat[2*NTOK];               // gate prob per flat (token*2+slot)
__device__ int   g_list[NEXP*NTOK];                // per-expert flat indices
__device__ int   g_cnt [NEXP];

// ---------------- tiny utility kernels ----------------
__global__ void zero_cnt_kernel() {
    if (threadIdx.x < NEXP) g_cnt[threadIdx.x] = 0;
}

// ---------------- generic SGEMM-TN: C[m,n] = sum_k A[m,k]*W[n,k] + bias[n] (+resid) ----------------
// a_mode: 0 -> use A param, 1 -> A = g_moe
// c_mode: 0 -> use C param, 1/2/3 -> C = g_lin + (c_mode-1)*NTOK*En
__global__ void __launch_bounds__(256, 2)
sgemm_tn(const float* __restrict__ A, const float* __restrict__ W,
         const float* __restrict__ bias, const float* __restrict__ resid,
         float* __restrict__ C, int M, int N, int K, int a_mode, int c_mode)
{
    __shared__ float As[16][128];
    __shared__ float Bs[16][128];

    const float* Ap = (a_mode == 0) ? A : g_moe;
    float*       Cp = (c_mode == 0) ? C : (g_lin + (size_t)(c_mode - 1) * NTOK * En);

    const int tid = threadIdx.x;
    const int m0  = blockIdx.y * 128;
    const int n0  = blockIdx.x * 128;
    const int tx  = tid & 15;
    const int ty  = tid >> 4;

    float acc[8][8];
    #pragma unroll
    for (int i = 0; i < 8; i++)
        #pragma unroll
        for (int j = 0; j < 8; j++) acc[i][j] = 0.f;

    for (int kt = 0; kt < K; kt += 16) {
        #pragma unroll
        for (int l = 0; l < 2; l++) {
            int f4  = l * 256 + tid;          // 0..511
            int row = f4 >> 2;
            int kc  = (f4 & 3) << 2;
            float4 a = *(const float4*)(Ap + (size_t)(m0 + row) * K + kt + kc);
            As[kc + 0][row] = a.x; As[kc + 1][row] = a.y;
            As[kc + 2][row] = a.z; As[kc + 3][row] = a.w;
            float4 b = *(const float4*)(W + (size_t)(n0 + row) * K + kt + kc);
            Bs[kc + 0][row] = b.x; Bs[kc + 1][row] = b.y;
            Bs[kc + 2][row] = b.z; Bs[kc + 3][row] = b.w;
        }
        __syncthreads();
        #pragma unroll
        for (int k = 0; k < 16; k++) {
            float ar[8], br[8];
            const float4* ap4 = (const float4*)&As[k][ty * 8];
            const float4* bp4 = (const float4*)&Bs[k][tx * 8];
            float4 a0 = ap4[0], a1 = ap4[1];
            float4 b0 = bp4[0], b1 = bp4[1];
            ar[0]=a0.x; ar[1]=a0.y; ar[2]=a0.z; ar[3]=a0.w;
            ar[4]=a1.x; ar[5]=a1.y; ar[6]=a1.z; ar[7]=a1.w;
            br[0]=b0.x; br[1]=b0.y; br[2]=b0.z; br[3]=b0.w;
            br[4]=b1.x; br[5]=b1.y; br[6]=b1.z; br[7]=b1.w;
            #pragma unroll
            for (int i = 0; i < 8; i++)
                #pragma unroll
                for (int j = 0; j < 8; j++)
                    acc[i][j] += ar[i] * br[j];
        }
        __syncthreads();
    }

    const bool has_res = (resid != nullptr);
    #pragma unroll
    for (int i = 0; i < 8; i++) {
        const int m = m0 + ty * 8 + i;
        float* crow = Cp + (size_t)m * N + n0 + tx * 8;
        const float* brow = bias + n0 + tx * 8;
        float v[8];
        #pragma unroll
        for (int j = 0; j < 8; j++) v[j] = acc[i][j] + brow[j];
        if (has_res) {
            const float* rrow = resid + (size_t)m * N + n0 + tx * 8;
            #pragma unroll
            for (int j = 0; j < 8; j++) v[j] += rrow[j];
        }
        *(float4*)(crow)     = make_float4(v[0], v[1], v[2], v[3]);
        *(float4*)(crow + 4) = make_float4(v[4], v[5], v[6], v[7]);
    }
}

// ---------------- RoPE + transpose: (tok, h*64+d) -> (bh, s, d) ----------------
__global__ void rope_transpose_kernel()
{
    int idx = blockIdx.x * blockDim.x + threadIdx.x;   // B*S*H*32 = 2^21 threads
    int i = idx & 31;
    int h = (idx >> 5) & 15;
    int s = (idx >> 9) & (Sn - 1);
    int b = idx >> 20;

    float expo = (float)(2 * i) / 64.0f;
    float inv  = powf(10000.0f, -expo);
    float ang  = (float)s * inv;
    float sn, cs;
    sincosf(ang, &sn, &cs);

    size_t in_base  = ((size_t)(b * Sn + s)) * En + h * 64;
    size_t out_base = ((size_t)((b * Hn + h) * Sn + s)) * 64;
    const size_t lin_stride = (size_t)NTOK * En;
    const size_t rot_stride = (size_t)Bn * Hn * Sn * Dn;

    // q
    {
        const float* src = g_lin + in_base;
        float x1 = src[i], x2 = src[i + 32];
        g_rot[out_base + i]      = x1 * cs - x2 * sn;
        g_rot[out_base + i + 32] = x2 * cs + x1 * sn;
    }
    // k
    {
        const float* src = g_lin + lin_stride + in_base;
        float x1 = src[i], x2 = src[i + 32];
        g_rot[rot_stride + out_base + i]      = x1 * cs - x2 * sn;
        g_rot[rot_stride + out_base + i + 32] = x2 * cs + x1 * sn;
    }
    // v (transpose only)
    {
        const float* src = g_lin + 2 * lin_stride + in_base;
        g_rot[2 * rot_stride + out_base + i]      = src[i];
        g_rot[2 * rot_stride + out_base + i + 32] = src[i + 32];
    }
}

// ---------------- flash attention: 1 thread = 1 query row ----------------
__global__ void __launch_bounds__(128)
attn_kernel()
{
    const int bh  = blockIdx.y;            // 0..31
    const int q0  = blockIdx.x * 128;
    const int tid = threadIdx.x;
    const size_t rot_stride = (size_t)Bn * Hn * Sn * Dn;
    const float* Qr = g_rot;
    const float* Kr = g_rot + rot_stride;
    const float* Vr = g_rot + 2 * rot_stride;
    const size_t base = (size_t)bh * Sn * Dn;

    __shared__ float Ks[64][64];
    __shared__ float Vs[64][64];

    float q[64], o[64];
    {
        const float4* qp = (const float4*)(Qr + base + (size_t)(q0 + tid) * 64);
        #pragma unroll
        for (int i = 0; i < 16; i++) {
            float4 t = qp[i];
            q[4*i+0] = t.x * 0.125f; q[4*i+1] = t.y * 0.125f;
            q[4*i+2] = t.z * 0.125f; q[4*i+3] = t.w * 0.125f;
        }
    }
    #pragma unroll
    for (int d = 0; d < 64; d++) o[d] = 0.f;
    float mx = -1e30f, l = 0.f;

    #pragma unroll 1
    for (int kt = 0; kt < Sn; kt += 64) {
        __syncthreads();
        const float4* kp = (const float4*)(Kr + base + (size_t)kt * 64);
        const float4* vp = (const float4*)(Vr + base + (size_t)kt * 64);
        float4* ks4 = (float4*)&Ks[0][0];
        float4* vs4 = (float4*)&Vs[0][0];
        #pragma unroll
        for (int i = 0; i < 8; i++) {
            int f4 = i * 128 + tid;            // 0..1023
            ks4[f4] = kp[f4];
            vs4[f4] = vp[f4];
        }
        __syncthreads();

        #pragma unroll 1
        for (int j0 = 0; j0 < 64; j0 += 16) {
            float s[16];
            #pragma unroll
            for (int j = 0; j < 16; j++) {
                const float4* kr = (const float4*)&Ks[j0 + j][0];
                float a0 = 0.f, a1 = 0.f, a2 = 0.f, a3 = 0.f;
                #pragma unroll
                for (int d4 = 0; d4 < 16; d4++) {
                    float4 kv = kr[d4];
                    a0 += q[4*d4+0] * kv.x; a1 += q[4*d4+1] * kv.y;
                    a2 += q[4*d4+2] * kv.z; a3 += q[4*d4+3] * kv.w;
                }
                s[j] = (a0 + a1) + (a2 + a3);
            }
            float tm = mx;
            #pragma unroll
            for (int j = 0; j < 16; j++) tm = fmaxf(tm, s[j]);
            float corr = __expf(mx - tm);
            mx = tm;
            l *= corr;
            #pragma unroll
            for (int d = 0; d < 64; d++) o[d] *= corr;
            #pragma unroll
            for (int j = 0; j < 16; j++) {
                float p = __expf(s[j] - mx);
                l += p;
                const float4* vr = (const float4*)&Vs[j0 + j][0];
                #pragma unroll
                for (int d4 = 0; d4 < 16; d4++) {
                    float4 vv = vr[d4];
                    o[4*d4+0] += p * vv.x; o[4*d4+1] += p * vv.y;
                    o[4*d4+2] += p * vv.z; o[4*d4+3] += p * vv.w;
                }
            }
        }
    }

    float invl = 1.f / l;
    int b = bh / Hn, h = bh % Hn;
    float4* op = (float4*)(g_attn + ((size_t)(b * Sn + q0 + tid)) * En + h * 64);
    #pragma unroll
    for (int i = 0; i < 16; i++) {
        float4 t;
        t.x = o[4*i+0] * invl; t.y = o[4*i+1] * invl;
        t.z = o[4*i+2] * invl; t.w = o[4*i+3] * invl;
        op[i] = t;
    }
}

// ---------------- gate logits + softmax + top-2 + dispatch ----------------
__global__ void __launch_bounds__(128)
gate_topk_kernel(const float* __restrict__ gw, const float* __restrict__ gb)
{
    const int warp = threadIdx.x >> 5;
    const int lane = threadIdx.x & 31;
    const int t = blockIdx.x * 4 + warp;

    float acc[NEXP];
    #pragma unroll
    for (int e = 0; e < NEXP; e++) acc[e] = 0.f;
    const float* xr = g_attn + (size_t)t * En;
    for (int i = lane; i < En; i += 32) {
        float xv = xr[i];
        #pragma unroll
        for (int e = 0; e < NEXP; e++) acc[e] += xv * gw[e * En + i];
    }
    #pragma unroll
    for (int e = 0; e < NEXP; e++) {
        #pragma unroll
        for (int off = 16; off; off >>= 1)
            acc[e] += __shfl_xor_sync(0xffffffffu, acc[e], off);
    }
    if (lane == 0) {
        float lg[NEXP];
        float m = -1e30f;
        #pragma unroll
        for (int e = 0; e < NEXP; e++) { lg[e] = acc[e] + gb[e]; m = fmaxf(m, lg[e]); }
        float sum = 0.f;
        #pragma unroll
        for (int e = 0; e < NEXP; e++) { lg[e] = __expf(lg[e] - m); sum += lg[e]; }
        float invs = 1.f / sum;
        int i0 = 0;
        #pragma unroll
        for (int e = 1; e < NEXP; e++) if (lg[e] > lg[i0]) i0 = e;
        int i1 = (i0 == 0) ? 1 : 0;
        #pragma unroll
        for (int e = 0; e < NEXP; e++) if (e != i0 && lg[e] > lg[i1]) i1 = e;

        int p0 = atomicAdd(&g_cnt[i0], 1);
        g_list[i0 * NTOK + p0] = t * 2;
        g_gateflat[t * 2] = lg[i0] * invs;
        int p1 = atomicAdd(&g_cnt[i1], 1);
        g_list[i1 * NTOK + p1] = t * 2 + 1;
        g_gateflat[t * 2 + 1] = lg[i1] * invs;
    }
}

// ---------------- grouped expert GEMM (gathered rows) ----------------
__global__ void __launch_bounds__(256, 2)
expert_gemm_kernel(const float* __restrict__ ew, const float* __restrict__ eb)
{
    const int e   = blockIdx.z;
    const int cnt = g_cnt[e];
    const int m0  = blockIdx.y * 128;
    if (m0 >= cnt) return;
    const int n0  = blockIdx.x * 128;

    __shared__ float As[16][128];
    __shared__ float Bs[16][128];
    __shared__ int   rowflat[128];
    __shared__ float rowgate[128];

    const int tid = threadIdx.x;
    if (tid < 128) {
        int m = m0 + tid;
        int fl = (m < cnt) ? g_list[e * NTOK + m] : 0;
        rowflat[tid] = fl;
        rowgate[tid] = (m < cnt) ? g_gateflat[fl] : 0.f;
    }
    __syncthreads();

    const float* W = ew + (size_t)e * En * En;
    const int tx = tid & 15;
    const int ty = tid >> 4;
    float acc[8][8];
    #pragma unroll
    for (int i = 0; i < 8; i++)
        #pragma unroll
        for (int j = 0; j < 8; j++) acc[i][j] = 0.f;

    for (int kt = 0; kt < En; kt += 16) {
        #pragma unroll
        for (int l = 0; l < 2; l++) {
            int f4  = l * 256 + tid;
            int row = f4 >> 2;
            int kc  = (f4 & 3) << 2;
            int tok = rowflat[row] >> 1;
            float4 a = *(const float4*)(g_attn + (size_t)tok * En + kt + kc);
            As[kc + 0][row] = a.x; As[kc + 1][row] = a.y;
            As[kc + 2][row] = a.z; As[kc + 3][row] = a.w;
            float4 b = *(const float4*)(W + (size_t)(n0 + row) * En + kt + kc);
            Bs[kc + 0][row] = b.x; Bs[kc + 1][row] = b.y;
            Bs[kc + 2][row] = b.z; Bs[kc + 3][row] = b.w;
        }
        __syncthreads();
        #pragma unroll
        for (int k = 0; k < 16; k++) {
            float ar[8], br[8];
            const float4* ap4 = (const float4*)&As[k][ty * 8];
            const float4* bp4 = (const float4*)&Bs[k][tx * 8];
            float4 a0 = ap4[0], a1 = ap4[1];
            float4 b0 = bp4[0], b1 = bp4[1];
            ar[0]=a0.x; ar[1]=a0.y; ar[2]=a0.z; ar[3]=a0.w;
            ar[4]=a1.x; ar[5]=a1.y; ar[6]=a1.z; ar[7]=a1.w;
            br[0]=b0.x; br[1]=b0.y; br[2]=b0.z; br[3]=b0.w;
            br[4]=b1.x; br[5]=b1.y; br[6]=b1.z; br[7]=b1.w;
            #pragma unroll
            for (int i = 0; i < 8; i++)
                #pragma unroll
                for (int j = 0; j < 8; j++)
                    acc[i][j] += ar[i] * br[j];
        }
        __syncthreads();
    }

    #pragma unroll
    for (int i = 0; i < 8; i++) {
        const int mloc = ty * 8 + i;
        if (m0 + mloc >= cnt) continue;
        const int fl = rowflat[mloc];
        const float gtv = rowgate[mloc];
        float* crow = g_sel + (size_t)fl * En + n0 + tx * 8;
        const float* brow = eb + (size_t)e * En + n0 + tx * 8;
        float v[8];
        #pragma unroll
        for (int j = 0; j < 8; j++) v[j] = gtv * (acc[i][j] + brow[j]);
        *(float4*)(crow)     = make_float4(v[0], v[1], v[2], v[3]);
        *(float4*)(crow + 4) = make_float4(v[4], v[5], v[6], v[7]);
    }
}

// ---------------- combine two expert slots ----------------
__global__ void combine_kernel()
{
    size_t i = (size_t)blockIdx.x * blockDim.x + threadIdx.x;  // over NTOK*256
    size_t row = i >> 8;
    size_t col = i & 255;
    const float4* s4 = (const float4*)g_sel;
    float4 a = s4[(2 * row) * 256 + col];
    float4 b = s4[(2 * row + 1) * 256 + col];
    float4 r;
    r.x = a.x + b.x; r.y = a.y + b.y; r.z = a.z + b.z; r.w = a.w + b.w;
    ((float4*)g_moe)[i] = r;
}

// ---------------- launch ----------------
extern "C" void kernel_launch(void* const* d_in, const int* in_sizes, int n_in,
                              void* d_out, int out_size)
{
    const float* x     = (const float*)d_in[0];
    const float* q_w   = (const float*)d_in[1];
    const float* q_b   = (const float*)d_in[2];
    const float* k_w   = (const float*)d_in[3];
    const float* k_b   = (const float*)d_in[4];
    const float* v_w   = (const float*)d_in[5];
    const float* v_b   = (const float*)d_in[6];
    const float* gatew = (const float*)d_in[7];
    const float* gateb = (const float*)d_in[8];
    const float* ew    = (const float*)d_in[9];
    const float* eb    = (const float*)d_in[10];
    const float* ffn_w = (const float*)d_in[11];
    const float* ffn_b = (const float*)d_in[12];
    float* out = (float*)d_out;

    dim3 gemm_grid(En / 128, NTOK / 128);   // (8, 32)

    zero_cnt_kernel<<<1, 32>>>();

    // Q, K, V projections -> g_lin slices (c_mode 1..3)
    sgemm_tn<<<gemm_grid, 256>>>(x, q_w, q_b, nullptr, nullptr, NTOK, En, En, 0, 1);
    sgemm_tn<<<gemm_grid, 256>>>(x, k_w, k_b, nullptr, nullptr, NTOK, En, En, 0, 2);
    sgemm_tn<<<gemm_grid, 256>>>(x, v_w, v_b, nullptr, nullptr, NTOK, En, En, 0, 3);

    rope_transpose_kernel<<<(Bn * Sn * Hn * 32) / 256, 256>>>();

    attn_kernel<<<dim3(Sn / 128, Bn * Hn), 128>>>();

    gate_topk_kernel<<<NTOK / 4, 128>>>(gatew, gateb);

    expert_gemm_kernel<<<dim3(En / 128, NTOK / 128, NEXP), 256>>>(ew, eb);

    combine_kernel<<<(NTOK * (En / 4)) / 256, 256>>>();

    // final FFN + bias + residual -> d_out  (a_mode=1: A = g_moe)
    sgemm_tn<<<gemm_grid, 256>>>(nullptr, ffn_w, ffn_b, x, out, NTOK, En, En, 1, 0);
}

// round 5
// speedup vs baseline: 1.4358x; 1.4313x over previous
#include <cuda_runtime.h>
#include <math.h>

#define Bn   2
#define Sn   2048
#define En   1024
#define Hn   16
#define Dn   64
#define NEXP 8
#define NTOK (Bn*Sn)          // 4096
#define BHn  (Bn*Hn)          // 32
#define ROTSTRIDE ((size_t)BHn*Sn*Dn)

// ---------------- scratch (device globals; no allocation) ----------------
__device__ float g_lin [(size_t)3*NTOK*En];
__device__ float g_rot [(size_t)3*BHn*Sn*Dn];
__device__ float g_probs[(size_t)BHn*Sn*Sn];       // 512 MB
__device__ float g_attn[(size_t)NTOK*En];
__device__ float g_sel [(size_t)2*NTOK*En];
__device__ float g_moe [(size_t)NTOK*En];
__device__ float g_gateflat[2*NTOK];
__device__ int   g_list[NEXP*NTOK];
__device__ int   g_cnt [NEXP];

__global__ void zero_cnt_kernel() {
    if (threadIdx.x < NEXP) g_cnt[threadIdx.x] = 0;
}

// ---------------- tf32 helpers ----------------
__device__ __forceinline__ unsigned f2tf(float x) {
    unsigned r;
    asm("cvt.rna.tf32.f32 %0, %1;" : "=r"(r) : "f"(x));
    return r;
}
__device__ __forceinline__ void mma8(float* c, const unsigned* a, const unsigned* b) {
    asm volatile(
        "mma.sync.aligned.m16n8k8.row.col.f32.tf32.tf32.f32 "
        "{%0,%1,%2,%3}, {%4,%5,%6,%7}, {%8,%9}, {%0,%1,%2,%3};\n"
        : "+f"(c[0]), "+f"(c[1]), "+f"(c[2]), "+f"(c[3])
        : "r"(a[0]), "r"(a[1]), "r"(a[2]), "r"(a[3]), "r"(b[0]), "r"(b[1]));
}

// ---------------- generic tf32 MMA GEMM ----------------
// C[z][m][n] = alpha*sum_k A[z][m][k]*B'[z][k][n] (+bias[n]) (+resid[m][n])
// BNN=0: B is [N][K] row-major.  BNN=1: B is [K][N] row-major.
// SPLIT=1: 3xTF32 fp32-accurate.  c_attn=1: scatter into head layout of Cg.
template<int BN, int SPLIT, int BNN>
__global__ void __launch_bounds__(256)
mma_gemm(const float* __restrict__ Ag, const float* __restrict__ Bg,
         const float* __restrict__ bias, const float* __restrict__ resid,
         float* __restrict__ Cg, int M, int N, int K,
         long long sAz, long long sBz, long long sCz,
         float alpha, int c_attn)
{
    constexpr int WC   = (BN == 128) ? 4 : 2;
    constexpr int MT   = (BN == 128) ? 4 : 2;
    constexpr int BSTR = BN + 4;
    constexpr int BLD  = (8 * BN) / 256;
    constexpr int BS_FLOATS = BNN ? 32 * BSTR : BN * 36;

    __shared__ float As[128][36];
    __shared__ float Bs[BS_FLOATS];

    const int z = blockIdx.z;
    const float* A = Ag + (size_t)z * sAz;
    const float* B = Bg + (size_t)z * sBz;

    const int tid  = threadIdx.x;
    const int lane = tid & 31;
    const int warp = tid >> 5;
    const int grp  = lane >> 2;
    const int qd   = lane & 3;
    const int m0   = blockIdx.y * 128;
    const int n0   = blockIdx.x * BN;
    const int m0w  = (warp / WC) * (16 * MT);
    const int n0w  = (warp % WC) * 32;

    float acc[MT][4][4];
    #pragma unroll
    for (int i = 0; i < MT; i++)
        #pragma unroll
        for (int j = 0; j < 4; j++)
            #pragma unroll
            for (int c = 0; c < 4; c++) acc[i][j][c] = 0.f;

    for (int kt = 0; kt < K; kt += 32) {
        #pragma unroll
        for (int l = 0; l < 4; l++) {
            int idx = l * 256 + tid;
            int r = idx >> 3, c = (idx & 7) << 2;
            *(float4*)&As[r][c] = *(const float4*)(A + (size_t)(m0 + r) * K + kt + c);
        }
        #pragma unroll
        for (int l = 0; l < BLD; l++) {
            int idx = l * 256 + tid;
            if (BNN) {
                int r = idx / (BN / 4), c = (idx % (BN / 4)) << 2;
                *(float4*)&Bs[r * BSTR + c] = *(const float4*)(B + (size_t)(kt + r) * N + n0 + c);
            } else {
                int r = idx >> 3, c = (idx & 7) << 2;
                *(float4*)&Bs[r * 36 + c] = *(const float4*)(B + (size_t)(n0 + r) * K + kt + c);
            }
        }
        __syncthreads();

        #pragma unroll
        for (int kk = 0; kk < 32; kk += 8) {
            unsigned bh[4][2], bl[4][2];
            #pragma unroll
            for (int nt = 0; nt < 4; nt++) {
                int n = n0w + nt * 8 + grp;
                float v0, v1;
                if (BNN) { v0 = Bs[(kk + qd) * BSTR + n]; v1 = Bs[(kk + qd + 4) * BSTR + n]; }
                else     { v0 = Bs[n * 36 + kk + qd];     v1 = Bs[n * 36 + kk + qd + 4]; }
                bh[nt][0] = f2tf(v0); bh[nt][1] = f2tf(v1);
                if (SPLIT) {
                    bl[nt][0] = f2tf(v0 - __uint_as_float(bh[nt][0]));
                    bl[nt][1] = f2tf(v1 - __uint_as_float(bh[nt][1]));
                }
            }
            #pragma unroll
            for (int mt = 0; mt < MT; mt++) {
                int r = m0w + mt * 16 + grp;
                float x0 = As[r][kk + qd],     x1 = As[r + 8][kk + qd];
                float x2 = As[r][kk + qd + 4], x3 = As[r + 8][kk + qd + 4];
                unsigned ah[4] = { f2tf(x0), f2tf(x1), f2tf(x2), f2tf(x3) };
                unsigned al[4];
                if (SPLIT) {
                    al[0] = f2tf(x0 - __uint_as_float(ah[0]));
                    al[1] = f2tf(x1 - __uint_as_float(ah[1]));
                    al[2] = f2tf(x2 - __uint_as_float(ah[2]));
                    al[3] = f2tf(x3 - __uint_as_float(ah[3]));
                }
                #pragma unroll
                for (int nt = 0; nt < 4; nt++) {
                    mma8(acc[mt][nt], ah, bh[nt]);
                    if (SPLIT) {
                        mma8(acc[mt][nt], al, bh[nt]);
                        mma8(acc[mt][nt], ah, bl[nt]);
                    }
                }
            }
        }
        __syncthreads();
    }

    #pragma unroll
    for (int mt = 0; mt < MT; mt++) {
        #pragma unroll
        for (int h = 0; h < 2; h++) {
            int r = m0 + m0w + mt * 16 + grp + h * 8;
            #pragma unroll
            for (int nt = 0; nt < 4; nt++) {
                int col = n0w + nt * 8 + 2 * qd;
                int gc  = n0 + col;
                float v0 = acc[mt][nt][2 * h + 0] * alpha;
                float v1 = acc[mt][nt][2 * h + 1] * alpha;
                if (bias)  { v0 += bias[gc]; v1 += bias[gc + 1]; }
                if (resid) {
                    const float* rr = resid + (size_t)r * N + gc;
                    v0 += rr[0]; v1 += rr[1];
                }
                float2* dst;
                if (c_attn) {
                    int bb = z >> 4, hh = z & 15;
                    dst = (float2*)(Cg + ((size_t)(bb * Sn + r)) * En + hh * 64 + gc);
                } else {
                    dst = (float2*)(Cg + (size_t)z * sCz + (size_t)r * N + gc);
                }
                *dst = make_float2(v0, v1);
            }
        }
    }
}

// ---------------- RoPE + transpose: (tok, h*64+d) -> (bh, s, d) ----------------
__global__ void rope_transpose_kernel()
{
    int idx = blockIdx.x * blockDim.x + threadIdx.x;
    int i = idx & 31;
    int h = (idx >> 5) & 15;
    int s = (idx >> 9) & (Sn - 1);
    int b = idx >> 20;

    float inv = powf(10000.0f, -(float)(2 * i) / 64.0f);
    float sn, cs;
    sincosf((float)s * inv, &sn, &cs);

    size_t in_base  = ((size_t)(b * Sn + s)) * En + h * 64;
    size_t out_base = ((size_t)((b * Hn + h) * Sn + s)) * 64;
    const size_t lin_stride = (size_t)NTOK * En;

    {
        const float* src = g_lin + in_base;
        float x1 = src[i], x2 = src[i + 32];
        g_rot[out_base + i]      = x1 * cs - x2 * sn;
        g_rot[out_base + i + 32] = x2 * cs + x1 * sn;
    }
    {
        const float* src = g_lin + lin_stride + in_base;
        float x1 = src[i], x2 = src[i + 32];
        g_rot[ROTSTRIDE + out_base + i]      = x1 * cs - x2 * sn;
        g_rot[ROTSTRIDE + out_base + i + 32] = x2 * cs + x1 * sn;
    }
    {
        const float* src = g_lin + 2 * lin_stride + in_base;
        g_rot[2 * ROTSTRIDE + out_base + i]      = src[i];
        g_rot[2 * ROTSTRIDE + out_base + i + 32] = src[i + 32];
    }
}

// ---------------- row softmax over g_probs (in place) ----------------
__global__ void __launch_bounds__(256)
softmax_kernel(float* __restrict__ probs)
{
    __shared__ float redm[8], reds[8];
    float4* p4 = (float4*)(probs + (size_t)blockIdx.x * Sn);
    const int tid = threadIdx.x;
    const int lane = tid & 31, warp = tid >> 5;

    float4 a = p4[tid], b = p4[tid + 256];
    float m = fmaxf(fmaxf(fmaxf(a.x, a.y), fmaxf(a.z, a.w)),
                    fmaxf(fmaxf(b.x, b.y), fmaxf(b.z, b.w)));
    #pragma unroll
    for (int o = 16; o; o >>= 1) m = fmaxf(m, __shfl_xor_sync(0xffffffffu, m, o));
    if (lane == 0) redm[warp] = m;
    __syncthreads();
    float mm = redm[0];
    #pragma unroll
    for (int w = 1; w < 8; w++) mm = fmaxf(mm, redm[w]);

    a.x = __expf(a.x - mm); a.y = __expf(a.y - mm);
    a.z = __expf(a.z - mm); a.w = __expf(a.w - mm);
    b.x = __expf(b.x - mm); b.y = __expf(b.y - mm);
    b.z = __expf(b.z - mm); b.w = __expf(b.w - mm);
    float s = (a.x + a.y + a.z + a.w) + (b.x + b.y + b.z + b.w);
    #pragma unroll
    for (int o = 16; o; o >>= 1) s += __shfl_xor_sync(0xffffffffu, s, o);
    if (lane == 0) reds[warp] = s;
    __syncthreads();
    float ss = 0.f;
    #pragma unroll
    for (int w = 0; w < 8; w++) ss += reds[w];
    float invs = 1.f / ss;

    a.x *= invs; a.y *= invs; a.z *= invs; a.w *= invs;
    b.x *= invs; b.y *= invs; b.z *= invs; b.w *= invs;
    p4[tid] = a; p4[tid + 256] = b;
}

// ---------------- gate logits + softmax + top-2 + dispatch (fp32) ----------------
__global__ void __launch_bounds__(128)
gate_topk_kernel(const float* __restrict__ gw, const float* __restrict__ gb)
{
    const int warp = threadIdx.x >> 5;
    const int lane = threadIdx.x & 31;
    const int t = blockIdx.x * 4 + warp;

    float acc[NEXP];
    #pragma unroll
    for (int e = 0; e < NEXP; e++) acc[e] = 0.f;
    const float* xr = g_attn + (size_t)t * En;
    for (int i = lane; i < En; i += 32) {
        float xv = xr[i];
        #pragma unroll
        for (int e = 0; e < NEXP; e++) acc[e] += xv * gw[e * En + i];
    }
    #pragma unroll
    for (int e = 0; e < NEXP; e++) {
        #pragma unroll
        for (int off = 16; off; off >>= 1)
            acc[e] += __shfl_xor_sync(0xffffffffu, acc[e], off);
    }
    if (lane == 0) {
        float lg[NEXP];
        float m = -1e30f;
        #pragma unroll
        for (int e = 0; e < NEXP; e++) { lg[e] = acc[e] + gb[e]; m = fmaxf(m, lg[e]); }
        float sum = 0.f;
        #pragma unroll
        for (int e = 0; e < NEXP; e++) { lg[e] = __expf(lg[e] - m); sum += lg[e]; }
        float invs = 1.f / sum;
        int i0 = 0;
        #pragma unroll
        for (int e = 1; e < NEXP; e++) if (lg[e] > lg[i0]) i0 = e;
        int i1 = (i0 == 0) ? 1 : 0;
        #pragma unroll
        for (int e = 0; e < NEXP; e++) if (e != i0 && lg[e] > lg[i1]) i1 = e;

        int p0 = atomicAdd(&g_cnt[i0], 1);
        g_list[i0 * NTOK + p0] = t * 2;
        g_gateflat[t * 2] = lg[i0] * invs;
        int p1 = atomicAdd(&g_cnt[i1], 1);
        g_list[i1 * NTOK + p1] = t * 2 + 1;
        g_gateflat[t * 2 + 1] = lg[i1] * invs;
    }
}

// ---------------- grouped expert GEMM (gathered rows, plain tf32 MMA) ----------------
__global__ void __launch_bounds__(256)
expert_mma(const float* __restrict__ ew, const float* __restrict__ eb)
{
    const int e   = blockIdx.z;
    const int cnt = g_cnt[e];
    const int m0  = blockIdx.y * 128;
    if (m0 >= cnt) return;
    const int n0  = blockIdx.x * 128;

    __shared__ float As[128][36];
    __shared__ float Bs[128 * 36];
    __shared__ int   rowflat[128];
    __shared__ float rowgate[128];

    const int tid = threadIdx.x;
    if (tid < 128) {
        int m = m0 + tid;
        int fl = (m < cnt) ? g_list[e * NTOK + m] : 0;
        rowflat[tid] = fl;
        rowgate[tid] = (m < cnt) ? g_gateflat[fl] : 0.f;
    }
    __syncthreads();

    const float* W = ew + (size_t)e * En * En;
    const int lane = tid & 31;
    const int warp = tid >> 5;
    const int grp  = lane >> 2;
    const int qd   = lane & 3;
    const int m0w  = (warp / 4) * 64;
    const int n0w  = (warp % 4) * 32;

    float acc[4][4][4];
    #pragma unroll
    for (int i = 0; i < 4; i++)
        #pragma unroll
        for (int j = 0; j < 4; j++)
            #pragma unroll
            for (int c = 0; c < 4; c++) acc[i][j][c] = 0.f;

    for (int kt = 0; kt < En; kt += 32) {
        #pragma unroll
        for (int l = 0; l < 4; l++) {
            int idx = l * 256 + tid;
            int r = idx >> 3, c = (idx & 7) << 2;
            int tok = rowflat[r] >> 1;
            *(float4*)&As[r][c] = *(const float4*)(g_attn + (size_t)tok * En + kt + c);
            *(float4*)&Bs[r * 36 + c] = *(const float4*)(W + (size_t)(n0 + r) * En + kt + c);
        }
        __syncthreads();
        #pragma unroll
        for (int kk = 0; kk < 32; kk += 8) {
            unsigned bh[4][2];
            #pragma unroll
            for (int nt = 0; nt < 4; nt++) {
                int n = n0w + nt * 8 + grp;
                bh[nt][0] = f2tf(Bs[n * 36 + kk + qd]);
                bh[nt][1] = f2tf(Bs[n * 36 + kk + qd + 4]);
            }
            #pragma unroll
            for (int mt = 0; mt < 4; mt++) {
                int r = m0w + mt * 16 + grp;
                unsigned ah[4] = { f2tf(As[r][kk + qd]),     f2tf(As[r + 8][kk + qd]),
                                   f2tf(As[r][kk + qd + 4]), f2tf(As[r + 8][kk + qd + 4]) };
                #pragma unroll
                for (int nt = 0; nt < 4; nt++) mma8(acc[mt][nt], ah, bh[nt]);
            }
        }
        __syncthreads();
    }

    #pragma unroll
    for (int mt = 0; mt < 4; mt++) {
        #pragma unroll
        for (int h = 0; h < 2; h++) {
            int mloc = m0w + mt * 16 + grp + h * 8;
            if (m0 + mloc >= cnt) continue;
            int fl = rowflat[mloc];
            float gtv = rowgate[mloc];
            #pragma unroll
            for (int nt = 0; nt < 4; nt++) {
                int gc = n0 + n0w + nt * 8 + 2 * qd;
                float v0 = gtv * (acc[mt][nt][2 * h + 0] + eb[(size_t)e * En + gc]);
                float v1 = gtv * (acc[mt][nt][2 * h + 1] + eb[(size_t)e * En + gc + 1]);
                *(float2*)(g_sel + (size_t)fl * En + gc) = make_float2(v0, v1);
            }
        }
    }
}

// ---------------- combine two expert slots ----------------
__global__ void combine_kernel()
{
    size_t i = (size_t)blockIdx.x * blockDim.x + threadIdx.x;  // NTOK*256
    size_t row = i >> 8;
    size_t col = i & 255;
    const float4* s4 = (const float4*)g_sel;
    float4 a = s4[(2 * row) * 256 + col];
    float4 b = s4[(2 * row + 1) * 256 + col];
    ((float4*)g_moe)[i] = make_float4(a.x + b.x, a.y + b.y, a.z + b.z, a.w + b.w);
}

// ---------------- launch ----------------
extern "C" void kernel_launch(void* const* d_in, const int* in_sizes, int n_in,
                              void* d_out, int out_size)
{
    const float* x     = (const float*)d_in[0];
    const float* q_w   = (const float*)d_in[1];
    const float* q_b   = (const float*)d_in[2];
    const float* k_w   = (const float*)d_in[3];
    const float* k_b   = (const float*)d_in[4];
    const float* v_w   = (const float*)d_in[5];
    const float* v_b   = (const float*)d_in[6];
    const float* gatew = (const float*)d_in[7];
    const float* gateb = (const float*)d_in[8];
    const float* ew    = (const float*)d_in[9];
    const float* eb    = (const float*)d_in[10];
    const float* ffn_w = (const float*)d_in[11];
    const float* ffn_b = (const float*)d_in[12];
    float* out = (float*)d_out;

    float *lin, *rot, *probs, *attn, *moe;
    cudaGetSymbolAddress((void**)&lin,   g_lin);
    cudaGetSymbolAddress((void**)&rot,   g_rot);
    cudaGetSymbolAddress((void**)&probs, g_probs);
    cudaGetSymbolAddress((void**)&attn,  g_attn);
    cudaGetSymbolAddress((void**)&moe,   g_moe);

    zero_cnt_kernel<<<1, 32>>>();

    // QKV projections (3xTF32): C -> g_lin slices
    dim3 pg(En / 128, NTOK / 128, 1);
    mma_gemm<128,1,0><<<pg, 256>>>(x, q_w, q_b, nullptr, lin,
                                   NTOK, En, En, 0, 0, 0, 1.f, 0);
    mma_gemm<128,1,0><<<pg, 256>>>(x, k_w, k_b, nullptr, lin + (size_t)NTOK * En,
                                   NTOK, En, En, 0, 0, 0, 1.f, 0);
    mma_gemm<128,1,0><<<pg, 256>>>(x, v_w, v_b, nullptr, lin + (size_t)2 * NTOK * En,
                                   NTOK, En, En, 0, 0, 0, 1.f, 0);

    rope_transpose_kernel<<<(Bn * Sn * Hn * 32) / 256, 256>>>();

    // scores = Q K^T / 8  (3xTF32), per head
    mma_gemm<128,1,0><<<dim3(Sn / 128, Sn / 128, BHn), 256>>>(
        rot, rot + ROTSTRIDE, nullptr, nullptr, probs,
        Sn, Sn, Dn, (long long)Sn * Dn, (long long)Sn * Dn, (long long)Sn * Sn,
        0.125f, 0);

    softmax_kernel<<<BHn * Sn, 256>>>(probs);

    // attn_out = P V  (3xTF32), scatter into (tok, E) head layout
    mma_gemm<64,1,1><<<dim3(1, Sn / 128, BHn), 256>>>(
        probs, rot + 2 * ROTSTRIDE, nullptr, nullptr, attn,
        Sn, Dn, Sn, (long long)Sn * Sn, (long long)Sn * Dn, 0,
        1.f, 1);

    gate_topk_kernel<<<NTOK / 4, 128>>>(gatew, gateb);

    expert_mma<<<dim3(En / 128, NTOK / 128, NEXP), 256>>>(ew, eb);

    combine_kernel<<<(NTOK * (En / 4)) / 256, 256>>>();

    // final FFN + bias + residual (plain tf32)
    mma_gemm<128,0,0><<<pg, 256>>>(moe, ffn_w, ffn_b, x, out,
                                   NTOK, En, En, 0, 0, 0, 1.f, 0);
}